// round 12
// baseline (speedup 1.0000x reference)
#include <cuda_runtime.h>
#include <cuda_bf16.h>
#include <math.h>
#include <stdint.h>

#define N_NODES   50000
#define NODE_DIM  128
#define IN_DIM    384
#define OUT_DIM   256
#define EPS       1e-5f
#define TILE_M    128
#define KC        64
#define NCH       6
#define NSTAGE    3
#define E_MAX     500000
#define THREADS   512

// ---- static device scratch (no allocs) ----
__device__ __nv_bfloat16 g_xn[(size_t)N_NODES * NODE_DIM];   // LN'd nodes, bf16
__device__ __nv_bfloat16 g_wb[(size_t)IN_DIM * OUT_DIM];     // W bf16, [k][n]
__device__ __nv_bfloat16 g_eb[(size_t)E_MAX * NODE_DIM];     // edge_attr bf16

// ---- smem layout ----
#define A_STRIDE   72                            // bf16 units (144 B rows, conflict-free)
#define B_STRIDE   264                           // bf16 units (528 B rows, conflict-free)
#define A_OFF(s)   ((s) * (TILE_M * A_STRIDE * 2))            // 3 x 18432 B
#define B_OFF(s)   (NSTAGE * TILE_M * A_STRIDE * 2 + (s) * (KC * B_STRIDE * 2))  // 3 x 33792 B
#define R_STRIDE   260                           // float units; 1040 B rows, float4-aligned
#define MISC_B     (NSTAGE * (TILE_M * A_STRIDE * 2 + KC * B_STRIDE * 2))        // 156672
#define SM_BIAS_B  (MISC_B)
#define SM_SN_B    (MISC_B + 1024)
#define SM_DN_B    (MISC_B + 1536)
#define SMEM_BYTES (MISC_B + 2048)               // 158720 B

static __device__ __forceinline__ void cp16(uint32_t dst, const void* src) {
    asm volatile("cp.async.cg.shared.global [%0], [%1], 16;" :: "r"(dst), "l"(src));
}
static __device__ __forceinline__ void ldsm4(uint32_t* r, uint32_t addr) {
    asm volatile("ldmatrix.sync.aligned.m8n8.x4.shared.b16 {%0,%1,%2,%3}, [%4];"
                 : "=r"(r[0]), "=r"(r[1]), "=r"(r[2]), "=r"(r[3]) : "r"(addr));
}
static __device__ __forceinline__ void ldsm4t(uint32_t* r, uint32_t addr) {
    asm volatile("ldmatrix.sync.aligned.m8n8.x4.trans.shared.b16 {%0,%1,%2,%3}, [%4];"
                 : "=r"(r[0]), "=r"(r[1]), "=r"(r[2]), "=r"(r[3]) : "r"(addr));
}
static __device__ __forceinline__ void mma_bf16(float* c, const uint32_t* a, const uint32_t* b) {
    asm volatile(
        "mma.sync.aligned.m16n8k16.row.col.f32.bf16.bf16.f32 "
        "{%0,%1,%2,%3}, {%4,%5,%6,%7}, {%8,%9}, {%0,%1,%2,%3};"
        : "+f"(c[0]), "+f"(c[1]), "+f"(c[2]), "+f"(c[3])
        : "r"(a[0]), "r"(a[1]), "r"(a[2]), "r"(a[3]), "r"(b[0]), "r"(b[1]));
}

// ---------------------------------------------------------------------------
// Kernel 1 (merged prep): node LN -> bf16 | W -> bf16 | edge_attr -> bf16
// ---------------------------------------------------------------------------
#define LN_BLOCKS ((N_NODES + 7) / 8)
#define W_BLOCKS  ((IN_DIM * OUT_DIM + 255) / 256)
__global__ __launch_bounds__(256) void prep_kernel(const float* __restrict__ x,
                                                   const float* __restrict__ gamma,
                                                   const float* __restrict__ beta,
                                                   const float* __restrict__ W,
                                                   const float* __restrict__ ea,
                                                   int E) {
    int b = blockIdx.x;
    if (b < LN_BLOCKS) {
        int row = b * 8 + (threadIdx.x >> 5);
        if (row >= N_NODES) return;
        int lane = threadIdx.x & 31;
        float4 v = ((const float4*)(x + (size_t)row * NODE_DIM))[lane];
        float s  = v.x + v.y + v.z + v.w;
        float ss = v.x*v.x + v.y*v.y + v.z*v.z + v.w*v.w;
        #pragma unroll
        for (int o = 16; o; o >>= 1) {
            s  += __shfl_xor_sync(0xffffffffu, s,  o);
            ss += __shfl_xor_sync(0xffffffffu, ss, o);
        }
        float mu  = s * (1.0f/128.0f);
        float inv = rsqrtf(ss * (1.0f/128.0f) - mu*mu + EPS);
        float4 g = ((const float4*)gamma)[lane];
        float4 bb = ((const float4*)beta)[lane];
        __nv_bfloat162 h0 = {__float2bfloat16_rn((v.x-mu)*inv*g.x + bb.x),
                             __float2bfloat16_rn((v.y-mu)*inv*g.y + bb.y)};
        __nv_bfloat162 h1 = {__float2bfloat16_rn((v.z-mu)*inv*g.z + bb.z),
                             __float2bfloat16_rn((v.w-mu)*inv*g.w + bb.w)};
        __nv_bfloat162* dst = (__nv_bfloat162*)(g_xn + (size_t)row * NODE_DIM);
        dst[2*lane]   = h0;
        dst[2*lane+1] = h1;
    } else if (b < LN_BLOCKS + W_BLOCKS) {
        int idx = (b - LN_BLOCKS) * 256 + threadIdx.x;
        if (idx < IN_DIM * OUT_DIM) g_wb[idx] = __float2bfloat16_rn(W[idx]);
    } else {
        int idx = (b - LN_BLOCKS - W_BLOCKS) * 256 + threadIdx.x;
        if (idx < E * (NODE_DIM / 4)) {
            float4 v = ((const float4*)ea)[idx];
            __nv_bfloat162 h0 = {__float2bfloat16_rn(v.x), __float2bfloat16_rn(v.y)};
            __nv_bfloat162 h1 = {__float2bfloat16_rn(v.z), __float2bfloat16_rn(v.w)};
            ((__nv_bfloat162*)g_eb)[2*idx]   = h0;
            ((__nv_bfloat162*)g_eb)[2*idx+1] = h1;
        }
    }
}

// ---------------------------------------------------------------------------
// Kernel 2: bf16 mma.sync GEMM (128 x 256 x 384), KC=64, fully unrolled
//           mainloop w/ hoisted addresses, warp-per-row fused epilogue
// ---------------------------------------------------------------------------
__global__ __launch_bounds__(THREADS, 1) void edge_kernel(const int*   __restrict__ ei,
                                                          const float* __restrict__ ea,
                                                          const float* __restrict__ bias,
                                                          const float* __restrict__ eg,
                                                          const float* __restrict__ eb,
                                                          float* __restrict__ out,
                                                          int E) {
    extern __shared__ __align__(16) char smc[];
    float* sm = (float*)smc;
    const uint32_t smb = (uint32_t)__cvta_generic_to_shared(smc);

    const int tid  = threadIdx.x;
    const int lane = tid & 31;
    const int wid  = tid >> 5;
    const int wm   = wid & 3;          // 4 M-blocks of 32
    const int wn   = wid >> 2;         // 4 N-blocks of 64
    const int qr   = lane >> 2;
    const int qc   = lane & 3;

    const int e0 = blockIdx.x * TILE_M;
    const int ne = min(TILE_M, E - e0);

    float* bias_s = (float*)(smc + SM_BIAS_B);
    int*   sN_s   = (int*)(smc + SM_SN_B);
    int*   dN_s   = (int*)(smc + SM_DN_B);

    if (tid < TILE_M) {
        int e = e0 + min(tid, ne - 1);
        sN_s[tid] = ei[e];
        dN_s[tid] = ei[E + e];
    }
    if (tid < 64) ((float4*)bias_s)[tid] = ((const float4*)bias)[tid];
    __syncthreads();

    // ---- hoisted per-thread cp.async addressing ----
    const int rowA0 = tid >> 3;              // 0..63
    const int rowA1 = rowA0 + 64;            // 64..127
    const int cA8   = (tid & 7) * 8;         // bf16 col offset within 64-chunk
    const uint32_t dstA0 = smb + (rowA0 * A_STRIDE + cA8) * 2;
    const uint32_t dstA1 = smb + (rowA1 * A_STRIDE + cA8) * 2;
    const __nv_bfloat16* aS0 = g_xn + (size_t)sN_s[rowA0] * NODE_DIM + cA8;
    const __nv_bfloat16* aS1 = g_xn + (size_t)sN_s[rowA1] * NODE_DIM + cA8;
    const __nv_bfloat16* aD0 = g_xn + (size_t)dN_s[rowA0] * NODE_DIM + cA8;
    const __nv_bfloat16* aD1 = g_xn + (size_t)dN_s[rowA1] * NODE_DIM + cA8;
    const __nv_bfloat16* aE0 = g_eb + (size_t)min(e0 + rowA0, E - 1) * NODE_DIM + cA8;
    const __nv_bfloat16* aE1 = g_eb + (size_t)min(e0 + rowA1, E - 1) * NODE_DIM + cA8;

    const int kB   = tid >> 5;               // 0..15
    const int cB8  = (tid & 31) * 8;
    const uint32_t dstB = smb + (kB * B_STRIDE + cB8) * 2;
    const __nv_bfloat16* wsrc = g_wb + (size_t)kB * OUT_DIM + cB8;

    // ---- hoisted ldmatrix base addresses (bf16-unit scale applied) ----
    const int a_row = (lane & 7) + ((lane >> 3) & 1) * 8;
    const int a_ks  = (lane >> 4) * 8;
    const int b_krw = (lane & 7) + ((lane >> 3) & 1) * 8;
    const int b_ns  = (lane >> 4) * 8;
    const uint32_t aBase = smb + ((wm * 32 + a_row) * A_STRIDE + a_ks) * 2;
    const uint32_t bBase = smb + (b_krw * B_STRIDE + wn * 64 + b_ns) * 2;

    float acc[2][8][4];
    #pragma unroll
    for (int mt = 0; mt < 2; mt++)
        #pragma unroll
        for (int nt = 0; nt < 8; nt++)
            #pragma unroll
            for (int q = 0; q < 4; q++) acc[mt][nt][q] = 0.f;

    // -------- fully-unrolled issue: all offsets compile-time --------
    auto issue = [&](const int i) {            // i is compile-time under unroll
        const int st = i % NSTAGE;
        const int ko = (i & 1) * KC;           // element offset within source row
        const __nv_bfloat16* s0 = (i < 2) ? aS0 : (i < 4) ? aD0 : aE0;
        const __nv_bfloat16* s1 = (i < 2) ? aS1 : (i < 4) ? aD1 : aE1;
        cp16(dstA0 + A_OFF(st), s0 + ko);
        cp16(dstA1 + A_OFF(st), s1 + ko);
        #pragma unroll
        for (int it = 0; it < 4; it++)
            cp16(dstB + B_OFF(st) + it * (16 * B_STRIDE * 2),
                 wsrc + (size_t)i * KC * OUT_DIM + it * (16 * OUT_DIM));
        asm volatile("cp.async.commit_group;");
    };

    issue(0);
    issue(1);

    #pragma unroll
    for (int i = 0; i < NCH; i++) {
        if (i == NCH - 1) asm volatile("cp.async.wait_group 0;");
        else              asm volatile("cp.async.wait_group 1;");
        __syncthreads();

        const int st = i % NSTAGE;
        const uint32_t Ab = aBase + A_OFF(st);
        const uint32_t Bb = bBase + B_OFF(st);

        #pragma unroll
        for (int ks = 0; ks < 4; ks++) {
            const int k0 = ks * 16;
            uint32_t a[2][4];
            #pragma unroll
            for (int mt = 0; mt < 2; mt++)
                ldsm4(a[mt], Ab + (mt * 16 * A_STRIDE + k0) * 2);
            uint32_t bf[4][4];
            #pragma unroll
            for (int ntt = 0; ntt < 4; ntt++)
                ldsm4t(bf[ntt], Bb + (k0 * B_STRIDE + ntt * 16) * 2);
            #pragma unroll
            for (int mt = 0; mt < 2; mt++)
                #pragma unroll
                for (int nt = 0; nt < 8; nt++)
                    mma_bf16(acc[mt][nt], a[mt], &bf[nt >> 1][(nt & 1) * 2]);
        }

        if (i + 2 < NCH) issue(i + 2);
    }
    __syncthreads();   // all staging reads done before raw aliases it

    // -------- fragments -> raw smem with bias + relu --------
    {
        float* raw = sm;
        #pragma unroll
        for (int mt = 0; mt < 2; mt++) {
            #pragma unroll
            for (int nt = 0; nt < 8; nt++) {
                int r0 = wm * 32 + mt * 16 + qr;
                int c0 = wn * 64 + nt * 8 + 2 * qc;
                raw[r0 * R_STRIDE + c0]           = fmaxf(acc[mt][nt][0] + bias_s[c0],     0.f);
                raw[r0 * R_STRIDE + c0 + 1]       = fmaxf(acc[mt][nt][1] + bias_s[c0 + 1], 0.f);
                raw[(r0 + 8) * R_STRIDE + c0]     = fmaxf(acc[mt][nt][2] + bias_s[c0],     0.f);
                raw[(r0 + 8) * R_STRIDE + c0 + 1] = fmaxf(acc[mt][nt][3] + bias_s[c0 + 1], 0.f);
            }
        }
    }
    __syncthreads();

    // -------- warp-per-row: gated residual + LN + coalesced store --------
    {
        const float4 g4 = ((const float4*)eg)[lane];
        const float4 b4 = ((const float4*)eb)[lane];
        #pragma unroll
        for (int rr = 0; rr < 8; rr++) {
            int r = wid * 8 + rr;
            if (r < ne) {
                float4 dl = *(float4*)&sm[r * R_STRIDE + lane * 4];
                float4 gt = *(float4*)&sm[r * R_STRIDE + 128 + lane * 4];
                float4 ev = ((const float4*)(ea + (size_t)(e0 + r) * NODE_DIM))[lane];
                float o[4];
                o[0] = ev.x + dl.x / (1.0f + __expf(-gt.x));
                o[1] = ev.y + dl.y / (1.0f + __expf(-gt.y));
                o[2] = ev.z + dl.z / (1.0f + __expf(-gt.z));
                o[3] = ev.w + dl.w / (1.0f + __expf(-gt.w));
                float sv = o[0] + o[1] + o[2] + o[3];
                float sq = o[0]*o[0] + o[1]*o[1] + o[2]*o[2] + o[3]*o[3];
                #pragma unroll
                for (int off = 16; off; off >>= 1) {
                    sv += __shfl_xor_sync(0xffffffffu, sv, off);
                    sq += __shfl_xor_sync(0xffffffffu, sq, off);
                }
                float mu  = sv * (1.0f / 128.0f);
                float inv = rsqrtf(sq * (1.0f / 128.0f) - mu * mu + EPS);
                float4 ov;
                ov.x = (o[0] - mu) * inv * g4.x + b4.x;
                ov.y = (o[1] - mu) * inv * g4.y + b4.y;
                ov.z = (o[2] - mu) * inv * g4.z + b4.z;
                ov.w = (o[3] - mu) * inv * g4.w + b4.w;
                ((float4*)(out + (size_t)(e0 + r) * NODE_DIM))[lane] = ov;
            }
        }
    }
}

// ---------------------------------------------------------------------------
extern "C" void kernel_launch(void* const* d_in, const int* in_sizes, int n_in,
                              void* d_out, int out_size) {
    const float* x  = (const float*)d_in[0];
    const int*   ei = (const int*)  d_in[1];
    const float* ea = (const float*)d_in[2];
    const float* W  = (const float*)d_in[3];
    const float* b  = (const float*)d_in[4];
    const float* ng = (const float*)d_in[5];
    const float* nb = (const float*)d_in[6];
    const float* eg = (const float*)d_in[7];
    const float* eb = (const float*)d_in[8];
    float* out = (float*)d_out;

    int E = in_sizes[2] / NODE_DIM;   // 500000

    int ea_blocks = (E * (NODE_DIM / 4) + 255) / 256;
    prep_kernel<<<LN_BLOCKS + W_BLOCKS + ea_blocks, 256>>>(x, ng, nb, W, ea, E);

    cudaFuncSetAttribute(edge_kernel, cudaFuncAttributeMaxDynamicSharedMemorySize, SMEM_BYTES);
    edge_kernel<<<(E + TILE_M - 1) / TILE_M, THREADS, SMEM_BYTES>>>(ei, ea, b, eg, eb, out, E);
}

// round 13
// speedup vs baseline: 1.4131x; 1.4131x over previous
#include <cuda_runtime.h>
#include <cuda_bf16.h>
#include <math.h>
#include <stdint.h>

#define N_NODES   50000
#define NODE_DIM  128
#define IN_DIM    384
#define OUT_DIM   256
#define EPS       1e-5f
#define TILE_M    64
#define KC        64
#define NCH       6
#define NSTAGE    2
#define E_MAX     500000
#define THREADS   256

// ---- static device scratch (no allocs) ----
__device__ __nv_bfloat16 g_xn[(size_t)N_NODES * NODE_DIM];   // LN'd nodes, bf16
__device__ __nv_bfloat16 g_wb[(size_t)IN_DIM * OUT_DIM];     // W bf16, [k][n]
__device__ __nv_bfloat16 g_eb[(size_t)E_MAX * NODE_DIM];     // edge_attr bf16

// ---- smem layout ----
#define A_STRIDE   72                            // bf16 units (144 B rows, conflict-free)
#define B_STRIDE   264                           // bf16 units (528 B rows, conflict-free)
#define A_OFF(s)   ((s) * (TILE_M * A_STRIDE * 2))            // 2 x 9216 B
#define B_OFF(s)   (NSTAGE * TILE_M * A_STRIDE * 2 + (s) * (KC * B_STRIDE * 2))  // 2 x 33792 B
#define R_STRIDE   260                           // float units; 1040 B rows, float4-aligned
#define MISC_B     (NSTAGE * (TILE_M * A_STRIDE * 2 + KC * B_STRIDE * 2))        // 86016
#define SM_BIAS_B  (MISC_B)
#define SM_SN_B    (MISC_B + 1024)
#define SM_DN_B    (MISC_B + 1536)
#define SMEM_BYTES (MISC_B + 2048)               // 88064 B -> 2 CTAs/SM

static __device__ __forceinline__ void cp16(uint32_t dst, const void* src) {
    asm volatile("cp.async.cg.shared.global [%0], [%1], 16;" :: "r"(dst), "l"(src));
}
static __device__ __forceinline__ void ldsm4(uint32_t* r, uint32_t addr) {
    asm volatile("ldmatrix.sync.aligned.m8n8.x4.shared.b16 {%0,%1,%2,%3}, [%4];"
                 : "=r"(r[0]), "=r"(r[1]), "=r"(r[2]), "=r"(r[3]) : "r"(addr));
}
static __device__ __forceinline__ void ldsm4t(uint32_t* r, uint32_t addr) {
    asm volatile("ldmatrix.sync.aligned.m8n8.x4.trans.shared.b16 {%0,%1,%2,%3}, [%4];"
                 : "=r"(r[0]), "=r"(r[1]), "=r"(r[2]), "=r"(r[3]) : "r"(addr));
}
static __device__ __forceinline__ void mma_bf16(float* c, const uint32_t* a, const uint32_t* b) {
    asm volatile(
        "mma.sync.aligned.m16n8k16.row.col.f32.bf16.bf16.f32 "
        "{%0,%1,%2,%3}, {%4,%5,%6,%7}, {%8,%9}, {%0,%1,%2,%3};"
        : "+f"(c[0]), "+f"(c[1]), "+f"(c[2]), "+f"(c[3])
        : "r"(a[0]), "r"(a[1]), "r"(a[2]), "r"(a[3]), "r"(b[0]), "r"(b[1]));
}

// ---------------------------------------------------------------------------
// Kernel 1 (merged prep): node LN -> bf16 | W -> bf16 | edge_attr -> bf16
// ---------------------------------------------------------------------------
#define LN_BLOCKS ((N_NODES + 7) / 8)
#define W_BLOCKS  ((IN_DIM * OUT_DIM + 255) / 256)
__global__ __launch_bounds__(256) void prep_kernel(const float* __restrict__ x,
                                                   const float* __restrict__ gamma,
                                                   const float* __restrict__ beta,
                                                   const float* __restrict__ W,
                                                   const float* __restrict__ ea,
                                                   int E) {
    int b = blockIdx.x;
    if (b < LN_BLOCKS) {
        int row = b * 8 + (threadIdx.x >> 5);
        if (row >= N_NODES) return;
        int lane = threadIdx.x & 31;
        float4 v = ((const float4*)(x + (size_t)row * NODE_DIM))[lane];
        float s  = v.x + v.y + v.z + v.w;
        float ss = v.x*v.x + v.y*v.y + v.z*v.z + v.w*v.w;
        #pragma unroll
        for (int o = 16; o; o >>= 1) {
            s  += __shfl_xor_sync(0xffffffffu, s,  o);
            ss += __shfl_xor_sync(0xffffffffu, ss, o);
        }
        float mu  = s * (1.0f/128.0f);
        float inv = rsqrtf(ss * (1.0f/128.0f) - mu*mu + EPS);
        float4 g = ((const float4*)gamma)[lane];
        float4 bb = ((const float4*)beta)[lane];
        __nv_bfloat162 h0 = {__float2bfloat16_rn((v.x-mu)*inv*g.x + bb.x),
                             __float2bfloat16_rn((v.y-mu)*inv*g.y + bb.y)};
        __nv_bfloat162 h1 = {__float2bfloat16_rn((v.z-mu)*inv*g.z + bb.z),
                             __float2bfloat16_rn((v.w-mu)*inv*g.w + bb.w)};
        __nv_bfloat162* dst = (__nv_bfloat162*)(g_xn + (size_t)row * NODE_DIM);
        dst[2*lane]   = h0;
        dst[2*lane+1] = h1;
    } else if (b < LN_BLOCKS + W_BLOCKS) {
        int idx = (b - LN_BLOCKS) * 256 + threadIdx.x;
        if (idx < IN_DIM * OUT_DIM) g_wb[idx] = __float2bfloat16_rn(W[idx]);
    } else {
        int idx = (b - LN_BLOCKS - W_BLOCKS) * 256 + threadIdx.x;
        if (idx < E * (NODE_DIM / 4)) {
            float4 v = ((const float4*)ea)[idx];
            __nv_bfloat162 h0 = {__float2bfloat16_rn(v.x), __float2bfloat16_rn(v.y)};
            __nv_bfloat162 h1 = {__float2bfloat16_rn(v.z), __float2bfloat16_rn(v.w)};
            ((__nv_bfloat162*)g_eb)[2*idx]   = h0;
            ((__nv_bfloat162*)g_eb)[2*idx+1] = h1;
        }
    }
}

// ---------------------------------------------------------------------------
// Kernel 2: bf16 mma.sync GEMM (64 x 256 x 384), 8 warps, warp tile 32x64,
//           2-stage cp.async, 2 CTAs/SM, warp-per-row fused epilogue
// ---------------------------------------------------------------------------
__global__ __launch_bounds__(THREADS, 2) void edge_kernel(const int*   __restrict__ ei,
                                                          const float* __restrict__ ea,
                                                          const float* __restrict__ bias,
                                                          const float* __restrict__ eg,
                                                          const float* __restrict__ eb,
                                                          float* __restrict__ out,
                                                          int E) {
    extern __shared__ __align__(16) char smc[];
    float* sm = (float*)smc;
    const uint32_t smb = (uint32_t)__cvta_generic_to_shared(smc);

    const int tid  = threadIdx.x;
    const int lane = tid & 31;
    const int wid  = tid >> 5;
    const int wm   = wid & 1;          // 2 M-blocks of 32
    const int wn   = wid >> 1;         // 4 N-blocks of 64
    const int qr   = lane >> 2;
    const int qc   = lane & 3;

    const int e0 = blockIdx.x * TILE_M;
    const int ne = min(TILE_M, E - e0);

    float* bias_s = (float*)(smc + SM_BIAS_B);
    int*   sN_s   = (int*)(smc + SM_SN_B);
    int*   dN_s   = (int*)(smc + SM_DN_B);

    if (tid < TILE_M) {
        int e = e0 + min(tid, ne - 1);
        sN_s[tid] = ei[e];
        dN_s[tid] = ei[E + e];
    }
    if (tid < 64) ((float4*)bias_s)[tid] = ((const float4*)bias)[tid];
    __syncthreads();

    // -------- cp.async issue for chunk i (KC=64) into stage i%2 --------
    auto issue = [&](int i) {
        const int st = i & 1;
        {                                             // A: 512 cp16 (64 rows x 8)
            #pragma unroll
            for (int it = 0; it < 2; it++) {
                int idx = tid + THREADS * it;
                int row = idx >> 3, c = idx & 7;
                const __nv_bfloat16* src;
                if (i < 2)       src = g_xn + (size_t)sN_s[row] * NODE_DIM + i * KC;
                else if (i < 4)  src = g_xn + (size_t)dN_s[row] * NODE_DIM + (i - 2) * KC;
                else             src = g_eb + (size_t)min(e0 + row, E - 1) * NODE_DIM + (i - 4) * KC;
                cp16(smb + A_OFF(st) + (row * A_STRIDE + c * 8) * 2, src + c * 8);
            }
        }
        const __nv_bfloat16* Wb = g_wb + (size_t)i * KC * OUT_DIM;
        #pragma unroll
        for (int it = 0; it < 8; it++) {              // B: 2048 cp16 (64 rows x 32)
            int idx = tid + THREADS * it;
            int k = idx >> 5, c = idx & 31;
            cp16(smb + B_OFF(st) + (k * B_STRIDE + c * 8) * 2, Wb + k * OUT_DIM + c * 8);
        }
        asm volatile("cp.async.commit_group;");
    };

    float acc[2][8][4];
    #pragma unroll
    for (int mt = 0; mt < 2; mt++)
        #pragma unroll
        for (int nt = 0; nt < 8; nt++)
            #pragma unroll
            for (int q = 0; q < 4; q++) acc[mt][nt][q] = 0.f;

    // ldmatrix lane-address components (bf16 units)
    const int a_row = (lane & 7) + ((lane >> 3) & 1) * 8;
    const int a_ks  = (lane >> 4) * 8;
    const int b_krw = (lane & 7) + ((lane >> 3) & 1) * 8;
    const int b_ns  = (lane >> 4) * 8;

    issue(0);
    issue(1);

    #pragma unroll 1
    for (int i = 0; i < NCH; i++) {
        if (i == NCH - 1) asm volatile("cp.async.wait_group 0;");
        else              asm volatile("cp.async.wait_group 1;");
        __syncthreads();

        const int st = i & 1;
        const uint32_t Ab = smb + A_OFF(st);
        const uint32_t Bb = smb + B_OFF(st);

        #pragma unroll
        for (int ks = 0; ks < 4; ks++) {
            const int k0 = ks * 16;
            uint32_t a[2][4];
            #pragma unroll
            for (int mt = 0; mt < 2; mt++)
                ldsm4(a[mt], Ab + ((wm * 32 + mt * 16 + a_row) * A_STRIDE + k0 + a_ks) * 2);
            uint32_t bf[4][4];
            #pragma unroll
            for (int ntt = 0; ntt < 4; ntt++)
                ldsm4t(bf[ntt], Bb + ((k0 + b_krw) * B_STRIDE + wn * 64 + ntt * 16 + b_ns) * 2);
            #pragma unroll
            for (int mt = 0; mt < 2; mt++)
                #pragma unroll
                for (int nt = 0; nt < 8; nt++)
                    mma_bf16(acc[mt][nt], a[mt], &bf[nt >> 1][(nt & 1) * 2]);
        }

        // stage just consumed becomes the target of issue(i+2): ensure all
        // warps are done reading it before overwriting
        __syncthreads();
        if (i + 2 < NCH) issue(i + 2);
    }

    // -------- fragments -> raw smem with bias + relu --------
    {
        float* raw = sm;
        #pragma unroll
        for (int mt = 0; mt < 2; mt++) {
            #pragma unroll
            for (int nt = 0; nt < 8; nt++) {
                int r0 = wm * 32 + mt * 16 + qr;
                int c0 = wn * 64 + nt * 8 + 2 * qc;
                raw[r0 * R_STRIDE + c0]           = fmaxf(acc[mt][nt][0] + bias_s[c0],     0.f);
                raw[r0 * R_STRIDE + c0 + 1]       = fmaxf(acc[mt][nt][1] + bias_s[c0 + 1], 0.f);
                raw[(r0 + 8) * R_STRIDE + c0]     = fmaxf(acc[mt][nt][2] + bias_s[c0],     0.f);
                raw[(r0 + 8) * R_STRIDE + c0 + 1] = fmaxf(acc[mt][nt][3] + bias_s[c0 + 1], 0.f);
            }
        }
    }
    __syncthreads();

    // -------- warp-per-row: gated residual + LN + coalesced store --------
    {
        const float4 g4 = ((const float4*)eg)[lane];
        const float4 b4 = ((const float4*)eb)[lane];
        #pragma unroll
        for (int rr = 0; rr < 8; rr++) {
            int r = wid * 8 + rr;
            if (r < ne) {
                float4 dl = *(float4*)&sm[r * R_STRIDE + lane * 4];
                float4 gt = *(float4*)&sm[r * R_STRIDE + 128 + lane * 4];
                float4 ev = ((const float4*)(ea + (size_t)(e0 + r) * NODE_DIM))[lane];
                float o[4];
                o[0] = ev.x + dl.x / (1.0f + __expf(-gt.x));
                o[1] = ev.y + dl.y / (1.0f + __expf(-gt.y));
                o[2] = ev.z + dl.z / (1.0f + __expf(-gt.z));
                o[3] = ev.w + dl.w / (1.0f + __expf(-gt.w));
                float sv = o[0] + o[1] + o[2] + o[3];
                float sq = o[0]*o[0] + o[1]*o[1] + o[2]*o[2] + o[3]*o[3];
                #pragma unroll
                for (int off = 16; off; off >>= 1) {
                    sv += __shfl_xor_sync(0xffffffffu, sv, off);
                    sq += __shfl_xor_sync(0xffffffffu, sq, off);
                }
                float mu  = sv * (1.0f / 128.0f);
                float inv = rsqrtf(sq * (1.0f / 128.0f) - mu * mu + EPS);
                float4 ov;
                ov.x = (o[0] - mu) * inv * g4.x + b4.x;
                ov.y = (o[1] - mu) * inv * g4.y + b4.y;
                ov.z = (o[2] - mu) * inv * g4.z + b4.z;
                ov.w = (o[3] - mu) * inv * g4.w + b4.w;
                ((float4*)(out + (size_t)(e0 + r) * NODE_DIM))[lane] = ov;
            }
        }
    }
}

// ---------------------------------------------------------------------------
extern "C" void kernel_launch(void* const* d_in, const int* in_sizes, int n_in,
                              void* d_out, int out_size) {
    const float* x  = (const float*)d_in[0];
    const int*   ei = (const int*)  d_in[1];
    const float* ea = (const float*)d_in[2];
    const float* W  = (const float*)d_in[3];
    const float* b  = (const float*)d_in[4];
    const float* ng = (const float*)d_in[5];
    const float* nb = (const float*)d_in[6];
    const float* eg = (const float*)d_in[7];
    const float* eb = (const float*)d_in[8];
    float* out = (float*)d_out;

    int E = in_sizes[2] / NODE_DIM;   // 500000

    int ea_blocks = (E * (NODE_DIM / 4) + 255) / 256;
    prep_kernel<<<LN_BLOCKS + W_BLOCKS + ea_blocks, 256>>>(x, ng, nb, W, ea, E);

    cudaFuncSetAttribute(edge_kernel, cudaFuncAttributeMaxDynamicSharedMemorySize, SMEM_BYTES);
    edge_kernel<<<(E + TILE_M - 1) / TILE_M, THREADS, SMEM_BYTES>>>(ei, ea, b, eg, eb, out, E);
}